// round 17
// baseline (speedup 1.0000x reference)
#include <cuda_runtime.h>
#include <math.h>

// Problem constants (fixed by the dataset)
#define NB        8          // batch
#define C_IN      4
#define N_ETYPE   5
#define N_NTYPE   7
#define C_OUT     32
#define TEMB_CH   512
#define FAN       55         // N_ETYPE * (C_IN + N_NTYPE)
#define NMAX      400000

// Scatter accumulators (zero at load; gemv re-zeros what it consumes):
__device__ float    g_xsum[NMAX * N_ETYPE * 4];   // 32 MB
__device__ unsigned g_cnt [NMAX * N_ETYPE * 2];   // 16 MB
__device__ float    g_xa  [NMAX * 8];             // packed [x0..x3,nt,pad*3] rows
__device__ float    g_l2  [NB * TEMB_CH];         // lin2 pre-activation accum
__device__ float    g_inj [NB * C_OUT];
__device__ int      g_done0;                      // temb-block arrivals
__device__ int      g_done1;                      // inj-block arrivals
__device__ int      g_done2;                      // prep-block arrivals (reset by gemv)

// ---------------------------------------------------------------------------
// MEGA kernel, 512 threads/block:
//  blocks [0,64)            : temb lin1+lin2 partials -> g_l2, signal done0
//  blocks [64,72)           : spin done0==64; inj = swish(l2+b2) @ Wt -> g_inj
//  blocks [72,72+prep)      : pack g_xa rows ([x,nt] 32B), signal done2
//  blocks [72+prep,...)     : spin done2==prep; edge scatter via g_xa gather
// Deadlock-safe: waiters only depend on strictly lower block ids, and block
// dispatch respects bid order in wave 1 + work-steal afterwards.
// ---------------------------------------------------------------------------
__global__ void __launch_bounds__(512)
mega_kernel(const float* __restrict__ t,
            const float* __restrict__ W1,
            const float* __restrict__ b1,
            const float* __restrict__ W2,
            const float* __restrict__ b2,
            const float* __restrict__ Wt,
            const int* __restrict__ ei,
            const int* __restrict__ etype,
            const int* __restrict__ ntype,
            const float* __restrict__ x,
            int E, int N, int prep_blocks) {
    const int tid = threadIdx.x;

    if (blockIdx.x < 64) {
        __shared__ float emb[NB][128];
        __shared__ float h1s[NB][64];
        const int ks = blockIdx.x >> 3;
        const int bo = blockIdx.x & 7;
        const int b  = tid >> 6;
        const int j  = tid & 63;

        {
            float f = expf(-(float)j * (logf(10000.0f) / 63.0f));
            float ang = t[b] * f;
            emb[b][j]      = sinf(ang);
            emb[b][j + 64] = cosf(ang);
        }
        __syncthreads();
        {
            float s = b1[ks * 64 + j];
            const float* w = W1 + ks * 64 + j;
            #pragma unroll 8
            for (int i = 0; i < 128; i++) s += emb[b][i] * w[(size_t)i * TEMB_CH];
            h1s[b][j] = s * (1.0f / (1.0f + expf(-s)));
        }
        __syncthreads();
        {
            float s = 0.0f;
            const float* w = W2 + (size_t)(ks * 64) * TEMB_CH + bo * 64 + j;
            #pragma unroll 8
            for (int k = 0; k < 64; k++) s += h1s[b][k] * w[(size_t)k * TEMB_CH];
            atomicAdd(g_l2 + b * TEMB_CH + bo * 64 + j, s);
        }
        __syncthreads();
        if (tid == 0) {
            __threadfence();
            atomicAdd(&g_done0, 1);
        }
        return;
    }

    if (blockIdx.x < 72) {
        __shared__ float sws[TEMB_CH];
        __shared__ float part[16][33];
        const int b = blockIdx.x - 64;

        if (tid == 0) {
            while (atomicAdd(&g_done0, 0) < 64) __nanosleep(200);
            __threadfence();
        }
        __syncthreads();

        for (int i = tid; i < TEMB_CH; i += 512) {
            float v = __ldcg(g_l2 + b * TEMB_CH + i) + b2[i];
            sws[i] = v * (1.0f / (1.0f + expf(-v)));
        }
        __syncthreads();
        for (int i = tid; i < TEMB_CH; i += 512)   // restore zero-invariant
            g_l2[b * TEMB_CH + i] = 0.0f;

        const int c  = tid & 31;
        const int ks = tid >> 5;                   // 0..15
        const float* sw = sws + ks * 32;
        const float* w  = Wt + (ks * 32) * C_OUT + c;
        float s = 0.0f;
        #pragma unroll 8
        for (int i = 0; i < 32; i++) s += sw[i] * w[i * C_OUT];
        part[ks][c] = s;
        __syncthreads();

        if (tid < 32) {
            float v = 0.0f;
            #pragma unroll
            for (int k = 0; k < 16; k++) v += part[k][tid];
            g_inj[b * C_OUT + tid] = v;
        }
        __syncthreads();
        if (tid == 0) {
            __threadfence();
            int r = atomicAdd(&g_done1, 1);
            if (r == 7) {
                atomicExch(&g_done0, 0);
                atomicExch(&g_done1, 0);
            }
        }
        return;
    }

    if (blockIdx.x < 72 + prep_blocks) {
        // ---- prep: pack [x, nt] into one 32B row per node ----
        int n = (blockIdx.x - 72) * 512 + tid;
        if (n < N) {
            float4 xv = *reinterpret_cast<const float4*>(x + (size_t)n * C_IN);
            float* row = g_xa + (size_t)n * 8;
            *reinterpret_cast<float4*>(row) = xv;
            reinterpret_cast<int*>(row)[4] = ntype[n];
        }
        __syncthreads();
        if (tid == 0) {
            __threadfence();
            atomicAdd(&g_done2, 1);
        }
        return;
    }

    // ---- edge scatter: wait for prep, then 2 edges per thread with a
    // single 32B g_xa gather per edge (x + nt share one sector). ----
    if (tid == 0) {
        while (atomicAdd(&g_done2, 0) < prep_blocks) __nanosleep(200);
        __threadfence();
    }
    __syncthreads();

    int e2 = ((blockIdx.x - 72 - prep_blocks) * blockDim.x + tid) * 2;
    if (e2 >= E) return;
    int2 rows = *reinterpret_cast<const int2*>(ei + e2);
    int2 cols = *reinterpret_cast<const int2*>(ei + E + e2);
    int2 ets  = *reinterpret_cast<const int2*>(etype + e2);

    const float* r0 = g_xa + (size_t)cols.x * 8;
    const float* r1 = g_xa + (size_t)cols.y * 8;
    float4 xv0 = *reinterpret_cast<const float4*>(r0);
    float4 xv1 = *reinterpret_cast<const float4*>(r1);
    int nt0 = reinterpret_cast<const int*>(r0)[4];
    int nt1 = reinterpret_cast<const int*>(r1)[4];

    size_t bk0 = (size_t)rows.x * N_ETYPE + ets.x;
    size_t bk1 = (size_t)rows.y * N_ETYPE + ets.y;

    asm volatile("red.global.add.v4.f32 [%0], {%1,%2,%3,%4};"
                 :: "l"(g_xsum + bk0 * 4), "f"(xv0.x), "f"(xv0.y), "f"(xv0.z), "f"(xv0.w)
                 : "memory");
    asm volatile("red.global.add.v4.f32 [%0], {%1,%2,%3,%4};"
                 :: "l"(g_xsum + bk1 * 4), "f"(xv1.x), "f"(xv1.y), "f"(xv1.z), "f"(xv1.w)
                 : "memory");
    atomicAdd(g_cnt + bk0 * 2 + (nt0 >> 2), 1u << ((nt0 & 3) * 8));
    atomicAdd(g_cnt + bk1 * 2 + (nt1 >> 2), 1u << ((nt1 & 3) * 8));
}

// ---------------------------------------------------------------------------
// u8 counter -> exact fp32 via PRMT magic number.
// ---------------------------------------------------------------------------
template <int K>
__device__ __forceinline__ float byte2f(unsigned w) {
    unsigned r;
    asm("prmt.b32 %0, %1, %2, %3;"
        : "=r"(r) : "r"(w), "r"(0x4B000000u), "n"(0x7540u | K));
    return __uint_as_float(r) - 8388608.0f;
}

// ---------------------------------------------------------------------------
// GEMV v10 (best measured, 46.7us): 4 nodes x 8 channels per thread.
// Warp-level LDS/node = 3.44; acc = 16 u64; 5 blocks/SM target.
// Block 0 also resets g_done2 (runs strictly after mega in stream order).
// ---------------------------------------------------------------------------
__global__ void __launch_bounds__(128, 4)
gemv_kernel(const float* __restrict__ Wc,
            const int* __restrict__ batch_id,
            float* __restrict__ out,
            int N) {
    __shared__ __align__(16) float Ws[FAN * C_OUT];   // pre-scaled by 0.2
    __shared__ float injs[NB * 33];
    const int tid = threadIdx.x;
    if (blockIdx.x == 0 && tid == 0) g_done2 = 0;     // replay invariant
    for (int i = tid; i < FAN * C_OUT; i += blockDim.x) Ws[i] = Wc[i] * 0.2f;
    for (int i = tid; i < NB * C_OUT; i += blockDim.x) {
        int b = i >> 5, c = i & 31;
        injs[b * 33 + c] = g_inj[i];
    }
    __syncthreads();

    const int gid  = blockIdx.x * blockDim.x + tid;
    const int h    = gid & 3;                 // channel quarter: [h*8, h*8+8)
    const int base = (gid >> 2) * 4;          // this group's 4 nodes
    if (base >= N) return;

    unsigned long long acc[4][4];             // 4 nodes x 8 channels (4 u64)
    #pragma unroll
    for (int nd = 0; nd < 4; nd++)
        #pragma unroll
        for (int k = 0; k < 4; k++) acc[nd][k] = 0ULL;

    float*    xp = g_xsum + (size_t)base * (N_ETYPE * 4);   // 16B aligned
    unsigned* cp = g_cnt  + (size_t)base * (N_ETYPE * 2);   // 16B aligned (base%4==0)

    #pragma unroll
    for (int et = 0; et < N_ETYPE; et++) {
        float a[4][11];
        #pragma unroll
        for (int nd = 0; nd < 4; nd++) {
            float4 v = *reinterpret_cast<float4*>(xp + nd * (N_ETYPE * 4) + et * 4);
            uint2  c = *reinterpret_cast<uint2*>(cp + nd * (N_ETYPE * 2) + et * 2);
            a[nd][0] = v.x; a[nd][1] = v.y; a[nd][2] = v.z; a[nd][3] = v.w;
            a[nd][4] = byte2f<0>(c.x); a[nd][5] = byte2f<1>(c.x);
            a[nd][6] = byte2f<2>(c.x); a[nd][7] = byte2f<3>(c.x);
            a[nd][8] = byte2f<0>(c.y); a[nd][9] = byte2f<1>(c.y);
            a[nd][10] = byte2f<2>(c.y);
        }

        #pragma unroll
        for (int j = 0; j < 11; j++) {
            const ulonglong2* Wv =
                reinterpret_cast<const ulonglong2*>(&Ws[(et * 11 + j) * C_OUT + h * 8]);
            ulonglong2 w0 = Wv[0];             // channels [h*8, h*8+4)
            ulonglong2 w1 = Wv[1];             // channels [h*8+4, h*8+8)
            #pragma unroll
            for (int nd = 0; nd < 4; nd++) {
                unsigned long long av;
                asm("mov.b64 %0, {%1, %1};" : "=l"(av) : "f"(a[nd][j]));
                asm("fma.rn.f32x2 %0, %1, %2, %0;" : "+l"(acc[nd][0]) : "l"(av), "l"(w0.x));
                asm("fma.rn.f32x2 %0, %1, %2, %0;" : "+l"(acc[nd][1]) : "l"(av), "l"(w0.y));
                asm("fma.rn.f32x2 %0, %1, %2, %0;" : "+l"(acc[nd][2]) : "l"(av), "l"(w1.x));
                asm("fma.rn.f32x2 %0, %1, %2, %0;" : "+l"(acc[nd][3]) : "l"(av), "l"(w1.y));
            }
        }
    }

    int4 bb = *reinterpret_cast<const int4*>(batch_id + base);
    const int bbl[4] = {bb.x, bb.y, bb.z, bb.w};
    #pragma unroll
    for (int nd = 0; nd < 4; nd++) {
        const float* iv = &injs[bbl[nd] * 33 + h * 8];
        float* op = out + (size_t)(base + nd) * C_OUT + h * 8;
        float l0, h0, l1, h1;
        asm("mov.b64 {%0, %1}, %2;" : "=f"(l0), "=f"(h0) : "l"(acc[nd][0]));
        asm("mov.b64 {%0, %1}, %2;" : "=f"(l1), "=f"(h1) : "l"(acc[nd][1]));
        float4 o;
        o.x = l0 + iv[0]; o.y = h0 + iv[1];
        o.z = l1 + iv[2]; o.w = h1 + iv[3];
        *reinterpret_cast<float4*>(op) = o;
        asm("mov.b64 {%0, %1}, %2;" : "=f"(l0), "=f"(h0) : "l"(acc[nd][2]));
        asm("mov.b64 {%0, %1}, %2;" : "=f"(l1), "=f"(h1) : "l"(acc[nd][3]));
        float4 p;
        p.x = l0 + iv[4]; p.y = h0 + iv[5];
        p.z = l1 + iv[6]; p.w = h1 + iv[7];
        *reinterpret_cast<float4*>(op + 4) = p;
    }

    // Re-zero: quarter h clears node base+h entirely (no overlap).
    {
        float*    zxp = xp + h * (N_ETYPE * 4);   // node h: 80B, 16B aligned
        unsigned* zcp = cp + h * (N_ETYPE * 2);   // node h: 40B, 8B aligned
        float4 z4 = make_float4(0.f, 0.f, 0.f, 0.f);
        #pragma unroll
        for (int i = 0; i < N_ETYPE; i++)
            *reinterpret_cast<float4*>(zxp + i * 4) = z4;
        uint2 z2 = make_uint2(0u, 0u);
        #pragma unroll
        for (int i = 0; i < N_ETYPE; i++)
            *reinterpret_cast<uint2*>(zcp + i * 2) = z2;
    }
}

// ---------------------------------------------------------------------------
// Inputs (metadata order):
//  0 x [N,4] f32        1 t [8] f32          2 edge_index [2,E] i32
//  3 edge_type [E] i32  4 node_type [N] i32  5 batch_id [N] i32
//  6 W_conv [55,32] f32 7 W1 [128,512]       8 b1 [512]
//  9 W2 [512,512]      10 b2 [512]          11 W_temb [512,32]
// Output: [N,32] f32
// ---------------------------------------------------------------------------
extern "C" void kernel_launch(void* const* d_in, const int* in_sizes, int n_in,
                              void* d_out, int out_size) {
    const float* x        = (const float*)d_in[0];
    const float* t        = (const float*)d_in[1];
    const int*   ei       = (const int*)d_in[2];
    const int*   etype    = (const int*)d_in[3];
    const int*   ntype    = (const int*)d_in[4];
    const int*   batch_id = (const int*)d_in[5];
    const float* W_conv   = (const float*)d_in[6];
    const float* W1       = (const float*)d_in[7];
    const float* b1       = (const float*)d_in[8];
    const float* W2       = (const float*)d_in[9];
    const float* b2       = (const float*)d_in[10];
    const float* W_temb   = (const float*)d_in[11];
    float* out = (float*)d_out;

    const int E = in_sizes[3];
    const int N = in_sizes[4];
    const int prep_blocks = (N + 511) / 512;
    const int edge_blocks = (E / 2 + 511) / 512;

    mega_kernel<<<72 + prep_blocks + edge_blocks, 512>>>(
        t, W1, b1, W2, b2, W_temb, ei, etype, ntype, x, E, N, prep_blocks);
    gemv_kernel<<<(N + 127) / 128, 128>>>(W_conv, batch_id, out, N);
}